// round 6
// baseline (speedup 1.0000x reference)
#include <cuda_runtime.h>
#include <cuda_bf16.h>
#include <cstdint>
#include <math.h>

#define D 1024
#define LSEQ 2048
#define BATCH 2
#define NH 16
#define HDIM 64
#define NROWS 4096  // BATCH*LSEQ

// ---------------------------------------------------------------------------
// Scratch (__device__ globals; allocation-free rule)
// ---------------------------------------------------------------------------
__device__ __align__(16) float g_q[(size_t)NROWS * D];
__device__ __align__(16) float g_k[(size_t)NROWS * D];
__device__ __align__(16) float g_v[(size_t)NROWS * D];
__device__ __align__(16) __nv_bfloat16 g_xhi[(size_t)NROWS * D];
__device__ __align__(16) __nv_bfloat16 g_xlo[(size_t)NROWS * D];
__device__ __align__(16) __nv_bfloat16 g_wthi[(size_t)4 * D * D];  // WT[n][k]
__device__ __align__(16) __nv_bfloat16 g_wtlo[(size_t)4 * D * D];
__device__ __align__(16) __nv_bfloat16 g_cxhi[(size_t)NROWS * D];
__device__ __align__(16) __nv_bfloat16 g_cxlo[(size_t)NROWS * D];

// ---------------------------------------------------------------------------
// mma.sync helpers (compute_103-legal: sm_80-era tensor core path)
// ---------------------------------------------------------------------------
static __device__ __forceinline__ uint32_t smem_u32(const void* p) {
    return (uint32_t)__cvta_generic_to_shared(p);
}

static __device__ __forceinline__ void ldmatrix_x4(uint32_t* d, uint32_t addr) {
    asm volatile("ldmatrix.sync.aligned.m8n8.x4.shared.b16 {%0,%1,%2,%3}, [%4];"
                 : "=r"(d[0]), "=r"(d[1]), "=r"(d[2]), "=r"(d[3])
                 : "r"(addr));
}

static __device__ __forceinline__ void mma_bf16(float* c, const uint32_t* a,
                                                uint32_t b0, uint32_t b1) {
    asm volatile(
        "mma.sync.aligned.m16n8k16.row.col.f32.bf16.bf16.f32 "
        "{%0,%1,%2,%3}, {%4,%5,%6,%7}, {%8,%9}, {%0,%1,%2,%3};"
        : "+f"(c[0]), "+f"(c[1]), "+f"(c[2]), "+f"(c[3])
        : "r"(a[0]), "r"(a[1]), "r"(a[2]), "r"(a[3]), "r"(b0), "r"(b1));
}

static __device__ __forceinline__ void cp16(uint32_t saddr, const void* gsrc) {
    asm volatile("cp.async.cg.shared.global [%0], [%1], 16;" :: "r"(saddr), "l"(gsrc));
}
#define CP_COMMIT() asm volatile("cp.async.commit_group;" ::: "memory")
#define CP_WAIT1()  asm volatile("cp.async.wait_group 1;" ::: "memory")

// ---------------------------------------------------------------------------
// bf16-split GEMM via mma.sync: C[4096,1024] = A @ W + bias (fp32-equivalent)
// CTA 128x128, 8 warps (2x4), warp tile 64x32, K-stage 32, cp.async 2-buffer.
// Smem rows padded to 40 bf16 (80B) -> conflict-free ldmatrix.
// ---------------------------------------------------------------------------
#define GT 256
#define KSTAGE 32
#define NST (D / KSTAGE)          // 32
#define ROWP 40                    // padded row length in bf16
#define TILE_E (128 * ROWP)        // 5120 elements per tile
#define BUF_E (4 * TILE_E)         // Ah, Al, Bh, Bl
#define GEMM_SMEM (2 * BUF_E * 2)  // bytes = 81920

__device__ __forceinline__ void gemm_core(
    const __nv_bfloat16* __restrict__ Ah, const __nv_bfloat16* __restrict__ Al,
    const __nv_bfloat16* __restrict__ Bh, const __nv_bfloat16* __restrict__ Bl,
    const float* __restrict__ bias, float* __restrict__ out, bool scatter_qkv) {
    extern __shared__ __nv_bfloat16 sm[];
    const uint32_t smb = smem_u32(sm);

    const int tid = threadIdx.x;
    const int warp = tid >> 5;
    const int lane = tid & 31;
    const int wm = warp >> 2;      // 0..1
    const int wn = warp & 3;       // 0..3
    const int bm = blockIdx.y * 128;
    const int bn = blockIdx.x * 128;

    const __nv_bfloat16* srcs[4] = {Ah + (size_t)bm * D, Al + (size_t)bm * D,
                                    Bh + (size_t)bn * D, Bl + (size_t)bn * D};

    // prefetch helper (inlined via lambda)
    auto prefetch = [&](int s, int buf) {
#pragma unroll
        for (int t = 0; t < 8; t++) {
            int idx = tid + t * GT;
            int tile = idx >> 9;
            int w = idx & 511;
            int r = w >> 2, c8 = w & 3;
            uint32_t dst = smb + 2u * (buf * BUF_E + tile * TILE_E + r * ROWP + c8 * 8);
            cp16(dst, srcs[tile] + (size_t)r * D + s * KSTAGE + c8 * 8);
        }
    };

    float c[4][4][4];
#pragma unroll
    for (int mi = 0; mi < 4; mi++)
#pragma unroll
        for (int ni = 0; ni < 4; ni++)
#pragma unroll
            for (int q = 0; q < 4; q++) c[mi][ni][q] = 0.0f;

    prefetch(0, 0);
    CP_COMMIT();
    prefetch(1, 1);
    CP_COMMIT();

    const int arow = (lane & 15);            // A ldmatrix row
    const int acol = (lane >> 4) << 3;       // A ldmatrix col offset
    const int brow = (lane & 7);             // B ldmatrix row (n)
    const int bcol = (lane >> 3) << 3;       // B ldmatrix col (k): 0,8,16,24

    for (int s = 0; s < NST; s++) {
        CP_WAIT1();
        __syncthreads();
        const int buf = s & 1;
        const uint32_t base = smb + 2u * (buf * BUF_E);
        const uint32_t aAh = base;
        const uint32_t aAl = base + 2u * TILE_E;
        const uint32_t aBh = base + 4u * TILE_E;
        const uint32_t aBl = base + 6u * TILE_E;

        // B fragments for the whole stage: x4 covers k=0..31
        uint32_t bh[4][4], bl[4][4];
#pragma unroll
        for (int ni = 0; ni < 4; ni++) {
            uint32_t off = 2u * ((wn * 32 + ni * 8 + brow) * ROWP + bcol);
            ldmatrix_x4(bh[ni], aBh + off);
            ldmatrix_x4(bl[ni], aBl + off);
        }

#pragma unroll
        for (int kk = 0; kk < 2; kk++) {
            uint32_t ah[4][4], al[4][4];
#pragma unroll
            for (int mi = 0; mi < 4; mi++) {
                uint32_t off = 2u * ((wm * 64 + mi * 16 + arow) * ROWP + kk * 16 + acol);
                ldmatrix_x4(ah[mi], aAh + off);
                ldmatrix_x4(al[mi], aAl + off);
            }
#pragma unroll
            for (int mi = 0; mi < 4; mi++)
#pragma unroll
                for (int ni = 0; ni < 4; ni++) {
                    mma_bf16(c[mi][ni], ah[mi], bh[ni][kk * 2], bh[ni][kk * 2 + 1]);
                    mma_bf16(c[mi][ni], ah[mi], bl[ni][kk * 2], bl[ni][kk * 2 + 1]);
                    mma_bf16(c[mi][ni], al[mi], bh[ni][kk * 2], bh[ni][kk * 2 + 1]);
                }
        }
        __syncthreads();
        if (s + 2 < NST) prefetch(s + 2, buf);
        CP_COMMIT();  // always commit to keep wait_group bookkeeping exact
    }

    // Epilogue: bias + store from registers
#pragma unroll
    for (int mi = 0; mi < 4; mi++) {
#pragma unroll
        for (int ni = 0; ni < 4; ni++) {
            int r0 = bm + wm * 64 + mi * 16 + (lane >> 2);
            int c0 = bn + wn * 32 + ni * 8 + (lane & 3) * 2;
            float bx = __ldg(bias + c0), by = __ldg(bias + c0 + 1);
#pragma unroll
            for (int h = 0; h < 2; h++) {
                int r = r0 + h * 8;
                float2 v;
                v.x = c[mi][ni][h * 2 + 0] + bx;
                v.y = c[mi][ni][h * 2 + 1] + by;
                if (scatter_qkv) {
                    int b_ = r >> 11, l = r & 2047;
                    int hh = c0 >> 6, d = c0 & 63;
                    *(float2*)(out + ((size_t)((b_ * NH + hh) * LSEQ + l)) * HDIM + d) = v;
                } else {
                    *(float2*)(out + (size_t)r * D + c0) = v;
                }
            }
        }
    }
}

__global__ void __launch_bounds__(GT) qkv_gemm(const float* __restrict__ bq,
                                               const float* __restrict__ bk,
                                               const float* __restrict__ bv) {
    int z = blockIdx.z;
    const __nv_bfloat16* Bh = g_wthi + (size_t)z * D * D;
    const __nv_bfloat16* Bl = g_wtlo + (size_t)z * D * D;
    const float* bias = (z == 0) ? bq : (z == 1) ? bk : bv;
    float* out = (z == 0) ? g_q : (z == 1) ? g_k : g_v;
    gemm_core(g_xhi, g_xlo, Bh, Bl, bias, out, true);
}

__global__ void __launch_bounds__(GT) oproj_gemm(const float* __restrict__ bo,
                                                 float* __restrict__ out) {
    gemm_core(g_cxhi, g_cxlo, g_wthi + (size_t)3 * D * D,
              g_wtlo + (size_t)3 * D * D, bo, out, false);
}

// ---------------------------------------------------------------------------
// Conversion kernels
// ---------------------------------------------------------------------------
__global__ void __launch_bounds__(256) convert_x_kernel(const float* __restrict__ x) {
    int i = blockIdx.x * 256 + threadIdx.x;  // over NROWS*D/4
    float4 v = ((const float4*)x)[i];
    __nv_bfloat16 h0 = __float2bfloat16(v.x), h1 = __float2bfloat16(v.y);
    __nv_bfloat16 h2 = __float2bfloat16(v.z), h3 = __float2bfloat16(v.w);
    __nv_bfloat16 l0 = __float2bfloat16(v.x - __bfloat162float(h0));
    __nv_bfloat16 l1 = __float2bfloat16(v.y - __bfloat162float(h1));
    __nv_bfloat16 l2 = __float2bfloat16(v.z - __bfloat162float(h2));
    __nv_bfloat16 l3 = __float2bfloat16(v.w - __bfloat162float(h3));
    ((__nv_bfloat162*)g_xhi)[i * 2 + 0] = __nv_bfloat162(h0, h1);
    ((__nv_bfloat162*)g_xhi)[i * 2 + 1] = __nv_bfloat162(h2, h3);
    ((__nv_bfloat162*)g_xlo)[i * 2 + 0] = __nv_bfloat162(l0, l1);
    ((__nv_bfloat162*)g_xlo)[i * 2 + 1] = __nv_bfloat162(l2, l3);
}

// Transpose + split all 4 weights: W[k][n] -> WT[n][k] hi/lo
__global__ void __launch_bounds__(256) convert_w_kernel(
    const float* __restrict__ Wq, const float* __restrict__ Wk,
    const float* __restrict__ Wv, const float* __restrict__ Wo) {
    __shared__ float t[32][33];
    int z = blockIdx.z;
    const float* W = (z == 0) ? Wq : (z == 1) ? Wk : (z == 2) ? Wv : Wo;
    __nv_bfloat16* oh = g_wthi + (size_t)z * D * D;
    __nv_bfloat16* ol = g_wtlo + (size_t)z * D * D;
    int kb = blockIdx.y * 32, nb = blockIdx.x * 32;
    int tx = threadIdx.x, ty = threadIdx.y;
#pragma unroll
    for (int i = ty; i < 32; i += 8)
        t[i][tx] = W[(size_t)(kb + i) * D + nb + tx];
    __syncthreads();
#pragma unroll
    for (int i = ty; i < 32; i += 8) {
        float v = t[tx][i];  // = W[kb+tx][nb+i]
        __nv_bfloat16 h = __float2bfloat16(v);
        __nv_bfloat16 l = __float2bfloat16(v - __bfloat162float(h));
        oh[(size_t)(nb + i) * D + kb + tx] = h;
        ol[(size_t)(nb + i) * D + kb + tx] = l;
    }
}

// ---------------------------------------------------------------------------
// Flash attention (softmax-one, causal). fp32 SIMT; epilogue emits ctx as
// bf16 hi/lo for the tensor-core output projection.
// ---------------------------------------------------------------------------
__global__ void __launch_bounds__(128) attn_kernel(const float* __restrict__ Qg,
                                                   const float* __restrict__ Kg,
                                                   const float* __restrict__ Vg) {
    extern __shared__ float smf[];
    float* Qt = smf;
    float* Kt = smf + 64 * 128;
    float* Vs = smf + 64 * 128 + 64 * 64;

    const int bh = blockIdx.y;
    const int qt = (gridDim.x - 1) - blockIdx.x;
    const int q0 = qt * 128;
    const float* Qb = Qg + (size_t)bh * LSEQ * HDIM;
    const float* Kb = Kg + (size_t)bh * LSEQ * HDIM;
    const float* Vb = Vg + (size_t)bh * LSEQ * HDIM;

    const int tid = threadIdx.x;
    const int warp = tid >> 5, lane = tid & 31;
    const int rg = lane >> 3, cg = lane & 7;
    const int rowbase = warp * 32 + rg * 8;

#pragma unroll
    for (int it = 0; it < 16; it++) {
        int idx = tid + it * 128;
        int r = idx >> 4, c4 = idx & 15;
        float4 v = *(const float4*)(Qb + (size_t)(q0 + r) * HDIM + c4 * 4);
        int sr = (((r >> 2) ^ (c4 & 7)) << 2) + (r & 3);
        Qt[(c4 * 4 + 0) * 128 + sr] = v.x;
        Qt[(c4 * 4 + 1) * 128 + sr] = v.y;
        Qt[(c4 * 4 + 2) * 128 + sr] = v.z;
        Qt[(c4 * 4 + 3) * 128 + sr] = v.w;
    }

    float acc[8][8];
    float m_i[8], l_i[8];
    const float NEG_INF = __int_as_float(0xff800000);
#pragma unroll
    for (int i = 0; i < 8; i++) {
        m_i[i] = NEG_INF;
        l_i[i] = 0.0f;
#pragma unroll
        for (int j = 0; j < 8; j++) acc[i][j] = 0.0f;
    }
    __syncthreads();

    const int nkt = 2 * qt + 2;
    for (int kt = 0; kt < nkt; kt++) {
        const int k0 = kt * 64;
#pragma unroll
        for (int it = 0; it < 8; it++) {
            int idx = tid + it * 128;
            int j = idx >> 4, c4 = idx & 15;
            float4 kv = *(const float4*)(Kb + (size_t)(k0 + j) * HDIM + c4 * 4);
            int sj = (((j >> 2) ^ (c4 & 7)) << 2) + (j & 3);
            Kt[(c4 * 4 + 0) * 64 + sj] = kv.x;
            Kt[(c4 * 4 + 1) * 64 + sj] = kv.y;
            Kt[(c4 * 4 + 2) * 64 + sj] = kv.z;
            Kt[(c4 * 4 + 3) * 64 + sj] = kv.w;
            float4 vv = *(const float4*)(Vb + (size_t)(k0 + j) * HDIM + c4 * 4);
            *(float4*)(Vs + j * 64 + c4 * 4) = vv;
        }
        __syncthreads();

        float s[8][8];
#pragma unroll
        for (int i = 0; i < 8; i++)
#pragma unroll
            for (int j = 0; j < 8; j++) s[i][j] = 0.0f;

#pragma unroll 8
        for (int d = 0; d < 64; d++) {
            int sw = (d >> 2) & 7;
            float a[8], b[8];
            *(float4*)(a + 0) = *(float4*)(Qt + d * 128 + (((warp * 8 + rg * 2 + 0) ^ sw) << 2));
            *(float4*)(a + 4) = *(float4*)(Qt + d * 128 + (((warp * 8 + rg * 2 + 1) ^ sw) << 2));
            *(float4*)(b + 0) = *(float4*)(Kt + d * 64 + (((cg * 2 + 0) ^ sw) << 2));
            *(float4*)(b + 4) = *(float4*)(Kt + d * 64 + (((cg * 2 + 1) ^ sw) << 2));
#pragma unroll
            for (int i = 0; i < 8; i++)
#pragma unroll
                for (int j = 0; j < 8; j++) s[i][j] += a[i] * b[j];
        }

        const float scale = 0.125f;
        if (kt >= 2 * qt) {
#pragma unroll
            for (int i = 0; i < 8; i++) {
                int qrow = q0 + rowbase + i;
#pragma unroll
                for (int j = 0; j < 8; j++) {
                    int kcol = k0 + cg * 8 + j;
                    s[i][j] = (kcol <= qrow) ? s[i][j] * scale : NEG_INF;
                }
            }
        } else {
#pragma unroll
            for (int i = 0; i < 8; i++)
#pragma unroll
                for (int j = 0; j < 8; j++) s[i][j] *= scale;
        }

#pragma unroll
        for (int i = 0; i < 8; i++) {
            float mx = s[i][0];
#pragma unroll
            for (int j = 1; j < 8; j++) mx = fmaxf(mx, s[i][j]);
            mx = fmaxf(mx, __shfl_xor_sync(0xffffffffu, mx, 1));
            mx = fmaxf(mx, __shfl_xor_sync(0xffffffffu, mx, 2));
            mx = fmaxf(mx, __shfl_xor_sync(0xffffffffu, mx, 4));
            float mnew = fmaxf(m_i[i], mx);
            float corr = __expf(m_i[i] - mnew);
            m_i[i] = mnew;
            float rs = 0.0f;
#pragma unroll
            for (int j = 0; j < 8; j++) {
                s[i][j] = __expf(s[i][j] - mnew);
                rs += s[i][j];
            }
            rs += __shfl_xor_sync(0xffffffffu, rs, 1);
            rs += __shfl_xor_sync(0xffffffffu, rs, 2);
            rs += __shfl_xor_sync(0xffffffffu, rs, 4);
            l_i[i] = l_i[i] * corr + rs;
#pragma unroll
            for (int dd = 0; dd < 8; dd++) acc[i][dd] *= corr;
        }

#pragma unroll 1
        for (int jt = 0; jt < 8; jt++) {
            int src = (lane & 24) | jt;
#pragma unroll
            for (int jj = 0; jj < 8; jj++) {
                int j = jt * 8 + jj;
                float4 b0 = *(float4*)(Vs + j * 64 + cg * 8);
                float4 b1 = *(float4*)(Vs + j * 64 + cg * 8 + 4);
#pragma unroll
                for (int i = 0; i < 8; i++) {
                    float a = __shfl_sync(0xffffffffu, s[i][jj], src);
                    acc[i][0] += a * b0.x;
                    acc[i][1] += a * b0.y;
                    acc[i][2] += a * b0.z;
                    acc[i][3] += a * b0.w;
                    acc[i][4] += a * b1.x;
                    acc[i][5] += a * b1.y;
                    acc[i][6] += a * b1.z;
                    acc[i][7] += a * b1.w;
                }
            }
        }
        __syncthreads();
    }

    // Epilogue: write ctx as bf16 hi/lo pair in (B, L, D) layout
    const int b_ = bh >> 4, hh = bh & 15;
#pragma unroll
    for (int i = 0; i < 8; i++) {
        float inv = 1.0f / (1.0f + l_i[i]);
        int gr = q0 + rowbase + i;
        size_t o = ((size_t)(b_ * LSEQ + gr)) * D + hh * 64 + cg * 8;
        __nv_bfloat162 hv[4], lv[4];
#pragma unroll
        for (int j = 0; j < 4; j++) {
            float v0 = acc[i][j * 2 + 0] * inv;
            float v1 = acc[i][j * 2 + 1] * inv;
            __nv_bfloat16 h0 = __float2bfloat16(v0);
            __nv_bfloat16 h1 = __float2bfloat16(v1);
            hv[j] = __nv_bfloat162(h0, h1);
            lv[j] = __nv_bfloat162(__float2bfloat16(v0 - __bfloat162float(h0)),
                                   __float2bfloat16(v1 - __bfloat162float(h1)));
        }
        *(uint4*)(g_cxhi + o) = *(uint4*)hv;
        *(uint4*)(g_cxlo + o) = *(uint4*)lv;
    }
}

// ---------------------------------------------------------------------------
extern "C" void kernel_launch(void* const* d_in, const int* in_sizes, int n_in,
                              void* d_out, int out_size) {
    (void)in_sizes; (void)n_in; (void)out_size;
    const float* x  = (const float*)d_in[0];
    const float* Wq = (const float*)d_in[1];
    const float* bq = (const float*)d_in[2];
    const float* Wk = (const float*)d_in[3];
    const float* bk = (const float*)d_in[4];
    const float* Wv = (const float*)d_in[5];
    const float* bv = (const float*)d_in[6];
    const float* Wo = (const float*)d_in[7];
    const float* bo = (const float*)d_in[8];

    float* qp;
    float* kp;
    float* vp;
    cudaGetSymbolAddress((void**)&qp, g_q);
    cudaGetSymbolAddress((void**)&kp, g_k);
    cudaGetSymbolAddress((void**)&vp, g_v);

    static bool attr_done = false;
    if (!attr_done) {
        cudaFuncSetAttribute(qkv_gemm, cudaFuncAttributeMaxDynamicSharedMemorySize, GEMM_SMEM);
        cudaFuncSetAttribute(oproj_gemm, cudaFuncAttributeMaxDynamicSharedMemorySize, GEMM_SMEM);
        cudaFuncSetAttribute(attn_kernel, cudaFuncAttributeMaxDynamicSharedMemorySize, 65536);
        attr_done = true;
    }

    // 1. Split x into bf16 hi/lo
    convert_x_kernel<<<NROWS * D / 4 / 256, 256>>>(x);
    // 2. Transpose + split all 4 weight matrices
    convert_w_kernel<<<dim3(32, 32, 4), dim3(32, 8)>>>(Wq, Wk, Wv, Wo);
    // 3. QKV projections on tensor cores (scatter to b,h,l,d)
    qkv_gemm<<<dim3(8, 32, 3), GT, GEMM_SMEM>>>(bq, bk, bv);
    // 4. Flash attention (emits ctx hi/lo)
    attn_kernel<<<dim3(16, 32), 128, 65536>>>(qp, kp, vp);
    // 5. Output projection on tensor cores -> d_out
    oproj_gemm<<<dim3(8, 32), GT, GEMM_SMEM>>>(bo, (float*)d_out);
}

// round 13
// speedup vs baseline: 1.0952x; 1.0952x over previous
#include <cuda_runtime.h>
#include <cstdint>
#include <math.h>

#define D 1024
#define LSEQ 2048
#define BATCH 2
#define NH 16
#define HDIM 64
#define NROWS 4096  // BATCH*LSEQ
#define NSTAGES 64  // D / 16  (K-stages; R9/R10 bug was 16 here)

// Scratch (__device__ globals; allocation-free rule)
__device__ __align__(16) float g_q[(size_t)NROWS * D];
__device__ __align__(16) float g_k[(size_t)NROWS * D];
__device__ __align__(16) float g_v[(size_t)NROWS * D];
__device__ __align__(16) float g_ctx[(size_t)NROWS * D];

// ---------------------------------------------------------------------------
// fp32 GEMM: C[4096,1024] = A[4096,1024] @ W[1024,1024] + bias
// CTA 128x128, 256 threads, 8x8 thread tile, BK=16.
// Register-prefetch software pipelining hides gmem latency under compute.
// ---------------------------------------------------------------------------
template <bool SCATTER>
__device__ __forceinline__ void gemm_body(const float* __restrict__ A,
                                          const float* __restrict__ W,
                                          const float* __restrict__ bias,
                                          float* __restrict__ C) {
    __shared__ float As[16 * 132];  // transposed A tile, padded width 132
    __shared__ float Bs[16 * 128];

    const int tid = threadIdx.x;
    const int bm = blockIdx.y * 128;
    const int bn = blockIdx.x * 128;

    const int warp = tid >> 5, lane = tid & 31;
    const int wy = warp & 3, wx = warp >> 2;   // 4 x 2 warp grid
    const int ty = lane >> 3, tx = lane & 7;   // 4 x 8 thread grid
    const int row0 = wy * 32 + ty * 8;
    const int col0 = wx * 64 + tx * 8;

    const int ar = tid >> 2, ac4 = tid & 3;    // A: rows 0..63 (+64 second half)
    const int br = tid >> 5, bc4 = tid & 31;   // B: rows 0..7 (+8)

    float c[8][8];
#pragma unroll
    for (int i = 0; i < 8; i++)
#pragma unroll
        for (int j = 0; j < 8; j++) c[i][j] = 0.0f;

    // prefetch stage 0 into registers
    float4 pa0, pa1, pb0, pb1;
    pa0 = *(const float4*)(A + (size_t)(bm + ar) * D + ac4 * 4);
    pa1 = *(const float4*)(A + (size_t)(bm + ar + 64) * D + ac4 * 4);
    pb0 = *(const float4*)(W + (size_t)br * D + bn + bc4 * 4);
    pb1 = *(const float4*)(W + (size_t)(br + 8) * D + bn + bc4 * 4);

    for (int s = 0; s < NSTAGES; s++) {
        // store prefetched stage to smem (A transposed)
        As[(ac4 * 4 + 0) * 132 + ar] = pa0.x;
        As[(ac4 * 4 + 1) * 132 + ar] = pa0.y;
        As[(ac4 * 4 + 2) * 132 + ar] = pa0.z;
        As[(ac4 * 4 + 3) * 132 + ar] = pa0.w;
        As[(ac4 * 4 + 0) * 132 + ar + 64] = pa1.x;
        As[(ac4 * 4 + 1) * 132 + ar + 64] = pa1.y;
        As[(ac4 * 4 + 2) * 132 + ar + 64] = pa1.z;
        As[(ac4 * 4 + 3) * 132 + ar + 64] = pa1.w;
        *(float4*)(Bs + br * 128 + bc4 * 4) = pb0;
        *(float4*)(Bs + (br + 8) * 128 + bc4 * 4) = pb1;
        __syncthreads();

        // issue next stage's gmem loads; latency covered by compute below
        if (s + 1 < NSTAGES) {
            const int k0 = (s + 1) * 16;
            pa0 = *(const float4*)(A + (size_t)(bm + ar) * D + k0 + ac4 * 4);
            pa1 = *(const float4*)(A + (size_t)(bm + ar + 64) * D + k0 + ac4 * 4);
            pb0 = *(const float4*)(W + (size_t)(k0 + br) * D + bn + bc4 * 4);
            pb1 = *(const float4*)(W + (size_t)(k0 + br + 8) * D + bn + bc4 * 4);
        }

#pragma unroll
        for (int k = 0; k < 16; k++) {
            float a[8], b[8];
            *(float4*)(a + 0) = *(float4*)(As + k * 132 + row0);
            *(float4*)(a + 4) = *(float4*)(As + k * 132 + row0 + 4);
            *(float4*)(b + 0) = *(float4*)(Bs + k * 128 + col0);
            *(float4*)(b + 4) = *(float4*)(Bs + k * 128 + col0 + 4);
#pragma unroll
            for (int i = 0; i < 8; i++)
#pragma unroll
                for (int j = 0; j < 8; j++) c[i][j] += a[i] * b[j];
        }
        __syncthreads();
    }

    // Epilogue: bias + store
#pragma unroll
    for (int i = 0; i < 8; i++) {
        int m = bm + row0 + i;
#pragma unroll
        for (int jv = 0; jv < 2; jv++) {
            int n = bn + col0 + jv * 4;
            float4 v;
            v.x = c[i][jv * 4 + 0] + bias[n + 0];
            v.y = c[i][jv * 4 + 1] + bias[n + 1];
            v.z = c[i][jv * 4 + 2] + bias[n + 2];
            v.w = c[i][jv * 4 + 3] + bias[n + 3];
            if (SCATTER) {
                int b_ = m >> 11, l = m & 2047;
                int hh = n >> 6, d = n & 63;
                *(float4*)(C + ((size_t)((b_ * NH + hh) * LSEQ + l)) * HDIM + d) = v;
            } else {
                *(float4*)(C + (size_t)m * D + n) = v;
            }
        }
    }
}

__global__ void __launch_bounds__(256) qkv_kernel(
    const float* __restrict__ x,
    const float* __restrict__ Wq, const float* __restrict__ bq,
    const float* __restrict__ Wk, const float* __restrict__ bk,
    const float* __restrict__ Wv, const float* __restrict__ bv) {
    const float *W, *bias;
    float* out;
    if (blockIdx.z == 0) { W = Wq; bias = bq; out = g_q; }
    else if (blockIdx.z == 1) { W = Wk; bias = bk; out = g_k; }
    else { W = Wv; bias = bv; out = g_v; }
    gemm_body<true>(x, W, bias, out);
}

__global__ void __launch_bounds__(256) oproj_kernel(
    const float* __restrict__ Wo, const float* __restrict__ bo,
    float* __restrict__ out) {
    gemm_body<false>(g_ctx, Wo, bo, out);
}

// ---------------------------------------------------------------------------
// Flash attention (softmax-one, causal). BQ=128, BK=64, 256 threads (8 warps),
// 4x8 thread tiles. PV goes through smem P (no shfl broadcast chains).
// ---------------------------------------------------------------------------
#define PS_PITCH 68
#define ATTN_SMEM ((16384 + 128 * PS_PITCH) * 4)  // Qt+Kt+Vs+Ps bytes

__global__ void __launch_bounds__(256) attn_kernel(const float* __restrict__ Qg,
                                                   const float* __restrict__ Kg,
                                                   const float* __restrict__ Vg) {
    extern __shared__ float smf[];
    float* Qt = smf;                 // [64][128] d-major, swizzled   (8192)
    float* Kt = smf + 8192;          // [64][64]  d-major, swizzled   (4096)
    float* Vs = smf + 12288;         // [64][64]  native              (4096)
    float* Ps = smf + 16384;         // [128][68] row-major P tile

    const int bh = blockIdx.y;                    // b*NH + h
    const int qt = (gridDim.x - 1) - blockIdx.x;  // heavy tiles first
    const int q0 = qt * 128;
    const float* Qb = Qg + (size_t)bh * LSEQ * HDIM;
    const float* Kb = Kg + (size_t)bh * LSEQ * HDIM;
    const float* Vb = Vg + (size_t)bh * LSEQ * HDIM;

    const int tid = threadIdx.x;
    const int warp = tid >> 5, lane = tid & 31;
    const int rg = lane >> 3, cg = lane & 7;
    const int rowbase = warp * 16 + rg * 4;   // first local q-row of this thread
    const int g0 = warp * 4 + rg;             // float4 row-group for Qt reads

    // Load Q tile (128 x 64) transposed into Qt[d][r] with XOR swizzle
#pragma unroll
    for (int it = 0; it < 8; it++) {
        int idx = tid + it * 256;
        int r = idx >> 4, c4 = idx & 15;
        float4 v = *(const float4*)(Qb + (size_t)(q0 + r) * HDIM + c4 * 4);
        int sr = (((r >> 2) ^ (c4 & 7)) << 2) + (r & 3);
        Qt[(c4 * 4 + 0) * 128 + sr] = v.x;
        Qt[(c4 * 4 + 1) * 128 + sr] = v.y;
        Qt[(c4 * 4 + 2) * 128 + sr] = v.z;
        Qt[(c4 * 4 + 3) * 128 + sr] = v.w;
    }

    float acc[4][8];
    float m_i[4], l_i[4];
    const float NEG_INF = __int_as_float(0xff800000);
#pragma unroll
    for (int i = 0; i < 4; i++) {
        m_i[i] = NEG_INF;
        l_i[i] = 0.0f;
#pragma unroll
        for (int j = 0; j < 8; j++) acc[i][j] = 0.0f;
    }
    __syncthreads();

    const int nkt = 2 * qt + 2;
    for (int kt = 0; kt < nkt; kt++) {
        const int k0 = kt * 64;
        // Load K (transposed+swizzled) and V (native): 64x16 chunks over 256 thr
#pragma unroll
        for (int it = 0; it < 4; it++) {
            int idx = tid + it * 256;
            int j = idx >> 4, c4 = idx & 15;
            float4 kv = *(const float4*)(Kb + (size_t)(k0 + j) * HDIM + c4 * 4);
            int sj = (((j >> 2) ^ (c4 & 7)) << 2) + (j & 3);
            Kt[(c4 * 4 + 0) * 64 + sj] = kv.x;
            Kt[(c4 * 4 + 1) * 64 + sj] = kv.y;
            Kt[(c4 * 4 + 2) * 64 + sj] = kv.z;
            Kt[(c4 * 4 + 3) * 64 + sj] = kv.w;
            float4 vv = *(const float4*)(Vb + (size_t)(k0 + j) * HDIM + c4 * 4);
            *(float4*)(Vs + j * 64 + c4 * 4) = vv;
        }
        __syncthreads();

        // S = Q K^T  (rows: 4 per thread, cols: 8 per thread)
        float s[4][8];
#pragma unroll
        for (int i = 0; i < 4; i++)
#pragma unroll
            for (int j = 0; j < 8; j++) s[i][j] = 0.0f;

#pragma unroll 8
        for (int d = 0; d < 64; d++) {
            int sw = (d >> 2) & 7;
            float4 a4 = *(float4*)(Qt + d * 128 + ((g0 ^ sw) << 2));
            float b[8];
            *(float4*)(b + 0) = *(float4*)(Kt + d * 64 + (((cg * 2 + 0) ^ sw) << 2));
            *(float4*)(b + 4) = *(float4*)(Kt + d * 64 + (((cg * 2 + 1) ^ sw) << 2));
            float a[4] = {a4.x, a4.y, a4.z, a4.w};
#pragma unroll
            for (int i = 0; i < 4; i++)
#pragma unroll
                for (int j = 0; j < 8; j++) s[i][j] += a[i] * b[j];
        }

        // Scale + causal mask (only diagonal-straddling tiles need the test)
        const float scale = 0.125f;  // 1/sqrt(64)
        if (kt >= 2 * qt) {
#pragma unroll
            for (int i = 0; i < 4; i++) {
                int qrow = q0 + rowbase + i;
#pragma unroll
                for (int j = 0; j < 8; j++) {
                    int kcol = k0 + cg * 8 + j;
                    s[i][j] = (kcol <= qrow) ? s[i][j] * scale : NEG_INF;
                }
            }
        } else {
#pragma unroll
            for (int i = 0; i < 4; i++)
#pragma unroll
                for (int j = 0; j < 8; j++) s[i][j] *= scale;
        }

        // Online softmax (each row spread across the 8 cg-lanes of the warp)
#pragma unroll
        for (int i = 0; i < 4; i++) {
            float mx = s[i][0];
#pragma unroll
            for (int j = 1; j < 8; j++) mx = fmaxf(mx, s[i][j]);
            mx = fmaxf(mx, __shfl_xor_sync(0xffffffffu, mx, 1));
            mx = fmaxf(mx, __shfl_xor_sync(0xffffffffu, mx, 2));
            mx = fmaxf(mx, __shfl_xor_sync(0xffffffffu, mx, 4));
            float mnew = fmaxf(m_i[i], mx);
            float corr = __expf(m_i[i] - mnew);
            m_i[i] = mnew;
            float rs = 0.0f;
#pragma unroll
            for (int j = 0; j < 8; j++) {
                s[i][j] = __expf(s[i][j] - mnew);
                rs += s[i][j];
            }
            rs += __shfl_xor_sync(0xffffffffu, rs, 1);
            rs += __shfl_xor_sync(0xffffffffu, rs, 2);
            rs += __shfl_xor_sync(0xffffffffu, rs, 4);
            l_i[i] = l_i[i] * corr + rs;
#pragma unroll
            for (int dd = 0; dd < 8; dd++) acc[i][dd] *= corr;
        }

        // Stage P to smem row-major (each thread owns contiguous cols)
#pragma unroll
        for (int i = 0; i < 4; i++) {
            float* pr = Ps + (rowbase + i) * PS_PITCH + cg * 8;
            *(float4*)(pr + 0) = make_float4(s[i][0], s[i][1], s[i][2], s[i][3]);
            *(float4*)(pr + 4) = make_float4(s[i][4], s[i][5], s[i][6], s[i][7]);
        }
        __syncthreads();

        // PV GEMM: acc[r][d] += P[r][j] * V[j][d]  (no shfl; LDS-broadcast a)
#pragma unroll 2
        for (int j4 = 0; j4 < 16; j4++) {
            float4 pa[4];
#pragma unroll
            for (int i = 0; i < 4; i++)
                pa[i] = *(float4*)(Ps + (rowbase + i) * PS_PITCH + j4 * 4);
#pragma unroll
            for (int jj = 0; jj < 4; jj++) {
                int j = j4 * 4 + jj;
                float4 b0 = *(float4*)(Vs + j * 64 + cg * 8);
                float4 b1 = *(float4*)(Vs + j * 64 + cg * 8 + 4);
#pragma unroll
                for (int i = 0; i < 4; i++) {
                    float p = (jj == 0) ? pa[i].x : (jj == 1) ? pa[i].y
                            : (jj == 2) ? pa[i].z : pa[i].w;
                    acc[i][0] += p * b0.x;
                    acc[i][1] += p * b0.y;
                    acc[i][2] += p * b0.z;
                    acc[i][3] += p * b0.w;
                    acc[i][4] += p * b1.x;
                    acc[i][5] += p * b1.y;
                    acc[i][6] += p * b1.z;
                    acc[i][7] += p * b1.w;
                }
            }
        }
        __syncthreads();  // protect Kt/Vs/Ps before next tile overwrites
    }

    // Write context in (B, L, D) row-major layout for the output projection
    const int b_ = bh >> 4, hh = bh & 15;
#pragma unroll
    for (int i = 0; i < 4; i++) {
        float inv = 1.0f / (1.0f + l_i[i]);  // softmax-one denominator
        int gr = q0 + rowbase + i;
        float* dst = g_ctx + ((size_t)(b_ * LSEQ + gr)) * D + hh * 64 + cg * 8;
        float4 o0, o1;
        o0.x = acc[i][0] * inv; o0.y = acc[i][1] * inv;
        o0.z = acc[i][2] * inv; o0.w = acc[i][3] * inv;
        o1.x = acc[i][4] * inv; o1.y = acc[i][5] * inv;
        o1.z = acc[i][6] * inv; o1.w = acc[i][7] * inv;
        *(float4*)dst = o0;
        *(float4*)(dst + 4) = o1;
    }
}

// ---------------------------------------------------------------------------
extern "C" void kernel_launch(void* const* d_in, const int* in_sizes, int n_in,
                              void* d_out, int out_size) {
    (void)in_sizes; (void)n_in; (void)out_size;
    const float* x  = (const float*)d_in[0];
    const float* Wq = (const float*)d_in[1];
    const float* bq = (const float*)d_in[2];
    const float* Wk = (const float*)d_in[3];
    const float* bk = (const float*)d_in[4];
    const float* Wv = (const float*)d_in[5];
    const float* bv = (const float*)d_in[6];
    const float* Wo = (const float*)d_in[7];
    const float* bo = (const float*)d_in[8];

    float* qp;
    float* kp;
    float* vp;
    cudaGetSymbolAddress((void**)&qp, g_q);
    cudaGetSymbolAddress((void**)&kp, g_k);
    cudaGetSymbolAddress((void**)&vp, g_v);

    static bool attr_done = false;
    if (!attr_done) {
        cudaFuncSetAttribute(attn_kernel, cudaFuncAttributeMaxDynamicSharedMemorySize,
                             ATTN_SMEM);
        attr_done = true;
    }

    // QKV projections (scatter to b,h,l,d)
    qkv_kernel<<<dim3(8, 32, 3), 256>>>(x, Wq, bq, Wk, bk, Wv, bv);
    // Flash attention (smem-P PV, 8 warps)
    attn_kernel<<<dim3(16, 32), 256, ATTN_SMEM>>>(qp, kp, vp);
    // Output projection straight into d_out
    oproj_kernel<<<dim3(8, 32), 256>>>(Wo, bo, (float*)d_out);
}